// round 3
// baseline (speedup 1.0000x reference)
#include <cuda_runtime.h>

#define NNF 128
#define MID 32
typedef unsigned long long u64;

// Staging + final tables
__device__ float g_stage[3][32][6][32];
__device__ float g_R[9][NNF];   // qs path projected through Wd_s (scaled)
__device__ float g_S[6][NNF];   // qv path projected through Wd_v (scaled)

// ---- packed f32x2 helpers -------------------------------------------------
__device__ __forceinline__ u64 pk2(float lo, float hi) {
    u64 r; asm("mov.b64 %0,{%1,%2};" : "=l"(r) : "f"(lo), "f"(hi)); return r;
}
__device__ __forceinline__ void upk2(u64 a, float& lo, float& hi) {
    asm("mov.b64 {%0,%1},%2;" : "=f"(lo), "=f"(hi) : "l"(a));
}
__device__ __forceinline__ u64 fma2(u64 a, u64 b, u64 c) {
    u64 d; asm("fma.rn.f32x2 %0,%1,%2,%3;" : "=l"(d) : "l"(a), "l"(b), "l"(c)); return d;
}
__device__ __forceinline__ u64 mul2(u64 a, u64 b) {
    u64 d; asm("mul.rn.f32x2 %0,%1,%2;" : "=l"(d) : "l"(a), "l"(b)); return d;
}
__device__ __forceinline__ u64 add2(u64 a, u64 b) {
    u64 d; asm("add.rn.f32x2 %0,%1,%2;" : "=l"(d) : "l"(a), "l"(b)); return d;
}

// ---------------------------------------------------------------------------
// Precompute stage 1: 96 blocks = 3 families x 32 u-slices. One element/thread.
// ---------------------------------------------------------------------------
__global__ void precompute1_kernel(
    const float* __restrict__ Wa_s, const float* __restrict__ Wa_v,
    const float* __restrict__ b_a,  const float* __restrict__ Wb_s,
    const float* __restrict__ Wb_v, const float* __restrict__ b_b,
    const float* __restrict__ W_ss, const float* __restrict__ W_vv,
    const float* __restrict__ W_sv, const float* __restrict__ W_vs)
{
    __shared__ float sA[MID], sB[MID], sC[MID], sAv[MID], sBv[MID];
    __shared__ float buf[6][32][33];

    const int tid = threadIdx.x;
    const int fam = blockIdx.x >> 5;
    const int u   = blockIdx.x & 31;
    if (tid < MID) {
        sA[tid]  = Wa_s[tid];
        sB[tid]  = Wb_s[tid];
        sC[tid]  = b_a[tid] + b_b[tid];
        sAv[tid] = Wa_v[tid];
        sBv[tid] = Wb_v[tid];
    }
    __syncthreads();

    const int v = tid >> 5;
    const int w = tid & 31;
    const int idx = u * 1024 + v * 32 + w;
    int nk;

    if (fam == 0) {
        float t = W_ss[idx];
        float Au = sA[u], Bu = sB[u], Cu = sC[u];
        float Av = sA[v], Bv = sB[v], Cv = sC[v];
        buf[0][v][w] = (Au * Av) * t;
        buf[1][v][w] = (Au * Bv + Bu * Av) * t;
        buf[2][v][w] = (Bu * Bv) * t;
        buf[3][v][w] = (Au * Cv + Cu * Av) * t;
        buf[4][v][w] = (Bu * Cv + Cu * Bv) * t;
        buf[5][v][w] = (Cu * Cv) * t;
        nk = 6;
    } else if (fam == 1) {
        float t = W_vv[idx];
        float Avu = sAv[u], Bvu = sBv[u], Avv = sAv[v], Bvv = sBv[v];
        buf[0][v][w] = (Avu * Avv) * t;
        buf[1][v][w] = (Avu * Bvv + Bvu * Avv) * t;
        buf[2][v][w] = (Bvu * Bvv) * t;
        nk = 3;
    } else {
        float tsv = W_sv[idx];
        float tvs = W_vs[idx];
        float Au = sA[u], Bu = sB[u], Cu = sC[u];
        float Avu = sAv[u], Bvu = sBv[u];
        float Av = sA[v], Bv = sB[v], Cv = sC[v];
        float Avv = sAv[v], Bvv = sBv[v];
        buf[0][v][w] = Au * Avv * tsv + Avu * Av * tvs;
        buf[1][v][w] = Bu * Avv * tsv + Avu * Bv * tvs;
        buf[2][v][w] = Cu * Avv * tsv + Avu * Cv * tvs;
        buf[3][v][w] = Au * Bvv * tsv + Bvu * Av * tvs;
        buf[4][v][w] = Bu * Bvv * tsv + Bvu * Bv * tvs;
        buf[5][v][w] = Cu * Bvv * tsv + Bvu * Cv * tvs;
        nk = 6;
    }
    __syncthreads();

    if (tid < nk * 32) {
        const int k = tid >> 5, ww = tid & 31;
        float s = 0.f;
        #pragma unroll
        for (int vv = 0; vv < 32; vv++) s += buf[k][vv][ww];
        g_stage[fam][u][k][ww] = s;
    }
}

// ---------------------------------------------------------------------------
// Precompute stage 2: u-reduction of stage buffer, then Wd projection + scales.
// ---------------------------------------------------------------------------
__global__ void precompute2_kernel(const float* __restrict__ Wd_s,
                                   const float* __restrict__ Wd_v)
{
    __shared__ float sM[9][32], sG[3][32], sH[3][32];
    const int tid = threadIdx.x;

    if (tid < 480) {
        const int w = tid & 31;
        float s = 0.f;
        if (tid < 192) {
            const int k = tid >> 5;
            #pragma unroll
            for (int u = 0; u < 32; u++) s += g_stage[0][u][k][w];
            sM[k][w] = s;
        } else if (tid < 288) {
            const int k = (tid - 192) >> 5;
            #pragma unroll
            for (int u = 0; u < 32; u++) s += g_stage[1][u][k][w];
            sM[6 + k][w] = s;
        } else {
            const int k = (tid - 288) >> 5;
            #pragma unroll
            for (int u = 0; u < 32; u++) s += g_stage[2][u][k][w];
            if (k < 3) sG[k][w] = s; else sH[k - 3][w] = s;
        }
    }
    __syncthreads();

    if (tid < NNF) {
        const int vp = tid;
        const double INV_SQRT3 = 0.5773502691896258;
        const double PW_QQ_S = 0.02209708691207961;   // sqrt(1/2048)
        const double PW_QQ_V = 0.03827327723098713;   // sqrt(3/2048)
        const double PW_DOWN = 0.011048543456039805;  // sqrt(1/8192)
        const float scR  = (float)(PW_DOWN * PW_QQ_S);
        const float scR3 = (float)(PW_DOWN * PW_QQ_S * INV_SQRT3);
        const float scS  = (float)(PW_DOWN * INV_SQRT3 * PW_QQ_V * INV_SQRT3);

        #pragma unroll
        for (int k = 0; k < 9; k++) {
            float s = 0.f;
            #pragma unroll
            for (int uu = 0; uu < MID; uu++) s += sM[k][uu] * Wd_s[uu * NNF + vp];
            g_R[k][vp] = s * (k < 6 ? scR : scR3);
        }
        #pragma unroll
        for (int k = 0; k < 3; k++) {
            float sg = 0.f, sh = 0.f;
            #pragma unroll
            for (int uu = 0; uu < MID; uu++) {
                float wd = Wd_v[uu * NNF + vp];
                sg += sG[k][uu] * wd;
                sh += sH[k][uu] * wd;
            }
            g_S[k][vp]     = sg * scS;
            g_S[3 + k][vp] = sh * scS;
        }
    }
}

// ---------------------------------------------------------------------------
// Energy kernel: warp per node-pair, explicit double-buffered prefetch.
// ---------------------------------------------------------------------------
struct PairData {
    float4 fsA, fsB;
    float4 fvA0, fvA1, fvA2;
    float4 fvB0, fvB1, fvB2;
    float4 q0A, qiA, q0B, qiB;
};

__device__ __forceinline__ void load_pair(
    PairData& d, const float* __restrict__ nf, const float* __restrict__ c0,
    const float* __restrict__ ci, int n0, int lane)
{
    const float* rowA = nf + (size_t)n0 * (4 * NNF);
    const float* rowB = rowA + 4 * NNF;
    const float* rvA  = rowA + NNF + 12 * lane;
    const float* rvB  = rowB + NNF + 12 * lane;
    d.fsA  = __ldcs((const float4*)(rowA + lane * 4));
    d.fsB  = __ldcs((const float4*)(rowB + lane * 4));
    d.fvA0 = __ldcs((const float4*)(rvA));
    d.fvA1 = __ldcs((const float4*)(rvA + 4));
    d.fvA2 = __ldcs((const float4*)(rvA + 8));
    d.fvB0 = __ldcs((const float4*)(rvB));
    d.fvB1 = __ldcs((const float4*)(rvB + 4));
    d.fvB2 = __ldcs((const float4*)(rvB + 8));
    d.q0A  = __ldcs((const float4*)(c0 + 4 * (size_t)n0));
    d.qiA  = __ldcs((const float4*)(ci + 4 * (size_t)n0));
    d.q0B  = __ldcs((const float4*)(c0 + 4 * (size_t)n0 + 4));
    d.qiB  = __ldcs((const float4*)(ci + 4 * (size_t)n0 + 4));
}

__device__ __forceinline__ float node_partial(
    const u64 R2[9][2], const u64 S2[6][2],
    float4 fs, const float* fv, float4 q0, float4 qi)
{
    const float a = qi.x, b = q0.x;
    const float g0 = qi.y, g1 = qi.z, g2 = qi.w;
    const float d0 = q0.y, d1 = q0.z, d2 = q0.w;
    const float ca2 = a * a, cab = a * b, cb2 = b * b;
    const float cg2 = g0 * g0 + g1 * g1 + g2 * g2;
    const float cgd = g0 * d0 + g1 * d1 + g2 * d2;
    const float cd2 = d0 * d0 + d1 * d1 + d2 * d2;

    const u64 C0 = pk2(ca2, ca2), C1 = pk2(cab, cab), C2 = pk2(cb2, cb2);
    const u64 CA = pk2(a, a),     CB = pk2(b, b);
    const u64 C6 = pk2(cg2, cg2), C7 = pk2(cgd, cgd), C8 = pk2(cd2, cd2);
    const u64 G0 = pk2(g0, g0), G1 = pk2(g1, g1), G2 = pk2(g2, g2);
    const u64 D0 = pk2(d0, d0), D1 = pk2(d1, d1), D2 = pk2(d2, d2);

    const u64 fs2[2] = { pk2(fs.x, fs.y), pk2(fs.z, fs.w) };

    u64 acc = pk2(0.f, 0.f);
    #pragma unroll
    for (int h = 0; h < 2; h++) {
        // qs path
        u64 t = fma2(C0, R2[0][h], R2[5][h]);
        t = fma2(C1, R2[1][h], t);
        t = fma2(C2, R2[2][h], t);
        t = fma2(CA, R2[3][h], t);
        t = fma2(CB, R2[4][h], t);
        t = fma2(C6, R2[6][h], t);
        t = fma2(C7, R2[7][h], t);
        t = fma2(C8, R2[8][h], t);
        acc = fma2(fs2[h], t, acc);
        // qv path: feature pair (2h, 2h+1)
        const u64 x0 = pk2(fv[6 * h + 0], fv[6 * h + 3]);
        const u64 x1 = pk2(fv[6 * h + 1], fv[6 * h + 4]);
        const u64 x2 = pk2(fv[6 * h + 2], fv[6 * h + 5]);
        u64 xg = mul2(G0, x0);
        xg = fma2(G1, x1, xg);
        xg = fma2(G2, x2, xg);
        u64 xd = mul2(D0, x0);
        xd = fma2(D1, x1, xd);
        xd = fma2(D2, x2, xd);
        u64 sg = fma2(CA, S2[0][h], S2[2][h]);
        sg = fma2(CB, S2[1][h], sg);
        u64 sh = fma2(CA, S2[3][h], S2[5][h]);
        sh = fma2(CB, S2[4][h], sh);
        acc = fma2(xg, sg, acc);
        acc = fma2(xd, sh, acc);
    }
    float lo, hi;
    upk2(acc, lo, hi);
    return lo + hi;
}

__device__ __forceinline__ void compute_store_pair(
    const PairData& d, const u64 R2[9][2], const u64 S2[6][2],
    float* __restrict__ out, int n0, int lane)
{
    const float fvA[12] = {d.fvA0.x, d.fvA0.y, d.fvA0.z, d.fvA0.w,
                           d.fvA1.x, d.fvA1.y, d.fvA1.z, d.fvA1.w,
                           d.fvA2.x, d.fvA2.y, d.fvA2.z, d.fvA2.w};
    const float fvB[12] = {d.fvB0.x, d.fvB0.y, d.fvB0.z, d.fvB0.w,
                           d.fvB1.x, d.fvB1.y, d.fvB1.z, d.fvB1.w,
                           d.fvB2.x, d.fvB2.y, d.fvB2.z, d.fvB2.w};
    const float accA = node_partial(R2, S2, d.fsA, fvA, d.q0A, d.qiA);
    const float accB = node_partial(R2, S2, d.fsB, fvB, d.q0B, d.qiB);

    u64 pr = pk2(accA, accB);
    #pragma unroll
    for (int off = 16; off; off >>= 1)
        pr = add2(pr, __shfl_down_sync(0xffffffffu, pr, off));
    if (lane == 0) {
        float2 o;
        upk2(pr, o.x, o.y);
        *(float2*)(out + n0) = o;
    }
}

__global__ void __launch_bounds__(256, 1) energy_kernel(
    const float* __restrict__ nf,
    const float* __restrict__ c0,
    const float* __restrict__ ci,
    float* __restrict__ out, int N)
{
    const int lane   = threadIdx.x & 31;
    const int warp   = (blockIdx.x * blockDim.x + threadIdx.x) >> 5;
    const int nwarps = (gridDim.x * blockDim.x) >> 5;

    // Tables packed along the feature axis: pairs (4l+0,4l+1) and (4l+2,4l+3).
    u64 R2[9][2], S2[6][2];
    #pragma unroll
    for (int k = 0; k < 9; k++) {
        float4 t = *(const float4*)&g_R[k][lane * 4];
        R2[k][0] = pk2(t.x, t.y); R2[k][1] = pk2(t.z, t.w);
    }
    #pragma unroll
    for (int k = 0; k < 6; k++) {
        float4 t = *(const float4*)&g_S[k][lane * 4];
        S2[k][0] = pk2(t.x, t.y); S2[k][1] = pk2(t.z, t.w);
    }

    const int pairs = N >> 1;

    // Ping-pong double-buffered pipeline: next pair's loads are issued before
    // computing the current pair, keeping 12 LDG.128 in flight per warp.
    int p = warp;
    if (p < pairs) {
        PairData bufA, bufB;
        load_pair(bufA, nf, c0, ci, 2 * p, lane);
        while (true) {
            const int p2 = p + nwarps;
            if (p2 < pairs) load_pair(bufB, nf, c0, ci, 2 * p2, lane);
            compute_store_pair(bufA, R2, S2, out, 2 * p, lane);
            if (p2 >= pairs) break;

            const int p3 = p2 + nwarps;
            if (p3 < pairs) load_pair(bufA, nf, c0, ci, 2 * p3, lane);
            compute_store_pair(bufB, R2, S2, out, 2 * p2, lane);
            if (p3 >= pairs) break;
            p = p3;
        }
    }

    // Odd-N tail (not hit for N=131072, kept for generality).
    if ((N & 1) && warp == 0) {
        const int n = N - 1;
        const float* row = nf + (size_t)n * (4 * NNF);
        float4 fs  = *(const float4*)(row + lane * 4);
        const float* rv = row + NNF + 12 * lane;
        float4 f0 = *(const float4*)(rv);
        float4 f1 = *(const float4*)(rv + 4);
        float4 f2 = *(const float4*)(rv + 8);
        float4 q0 = *(const float4*)(c0 + 4 * (size_t)n);
        float4 qi = *(const float4*)(ci + 4 * (size_t)n);
        const float fv[12] = {f0.x, f0.y, f0.z, f0.w, f1.x, f1.y, f1.z, f1.w,
                              f2.x, f2.y, f2.z, f2.w};
        float acc = node_partial(R2, S2, fs, fv, q0, qi);
        #pragma unroll
        for (int off = 16; off; off >>= 1)
            acc += __shfl_down_sync(0xffffffffu, acc, off);
        if (lane == 0) out[n] = acc;
    }
}

// ---------------------------------------------------------------------------
extern "C" void kernel_launch(void* const* d_in, const int* in_sizes, int n_in,
                              void* d_out, int out_size)
{
    const float* node_feats = (const float*)d_in[0];
    const float* charges_0  = (const float*)d_in[1];
    const float* charges_i  = (const float*)d_in[2];
    const float* Wa_s = (const float*)d_in[8];
    const float* Wa_v = (const float*)d_in[9];
    const float* b_a  = (const float*)d_in[10];
    const float* Wb_s = (const float*)d_in[11];
    const float* Wb_v = (const float*)d_in[12];
    const float* b_b  = (const float*)d_in[13];
    const float* W_ss = (const float*)d_in[14];
    const float* W_vv = (const float*)d_in[15];
    const float* W_sv = (const float*)d_in[16];
    const float* W_vs = (const float*)d_in[17];
    const float* Wd_s = (const float*)d_in[18];
    const float* Wd_v = (const float*)d_in[19];
    float* out = (float*)d_out;
    const int N = out_size;

    precompute1_kernel<<<96, 1024>>>(Wa_s, Wa_v, b_a, Wb_s, Wb_v, b_b,
                                     W_ss, W_vv, W_sv, W_vs);
    precompute2_kernel<<<1, 512>>>(Wd_s, Wd_v);
    energy_kernel<<<148, 256>>>(node_feats, charges_0, charges_i, out, N);
}

// round 4
// speedup vs baseline: 1.1090x; 1.1090x over previous
#include <cuda_runtime.h>
#include <cstdint>

#define NNF 128
#define MID 32
typedef unsigned long long u64;

// Staging + final tables
__device__ float g_stage[3][32][6][32];
__device__ float g_R[9][NNF];
__device__ float g_S[6][NNF];

// ---- packed f32x2 helpers -------------------------------------------------
__device__ __forceinline__ u64 pk2(float lo, float hi) {
    u64 r; asm("mov.b64 %0,{%1,%2};" : "=l"(r) : "f"(lo), "f"(hi)); return r;
}
__device__ __forceinline__ void upk2(u64 a, float& lo, float& hi) {
    asm("mov.b64 {%0,%1},%2;" : "=f"(lo), "=f"(hi) : "l"(a));
}
__device__ __forceinline__ u64 fma2(u64 a, u64 b, u64 c) {
    u64 d; asm("fma.rn.f32x2 %0,%1,%2,%3;" : "=l"(d) : "l"(a), "l"(b), "l"(c)); return d;
}
__device__ __forceinline__ u64 mul2(u64 a, u64 b) {
    u64 d; asm("mul.rn.f32x2 %0,%1,%2;" : "=l"(d) : "l"(a), "l"(b)); return d;
}
__device__ __forceinline__ u64 add2(u64 a, u64 b) {
    u64 d; asm("add.rn.f32x2 %0,%1,%2;" : "=l"(d) : "l"(a), "l"(b)); return d;
}

// ---- mbarrier / bulk-async helpers ----------------------------------------
__device__ __forceinline__ uint32_t smem_u32(const void* p) {
    uint32_t a;
    asm("{ .reg .u64 t; cvta.to.shared.u64 t, %1; cvt.u32.u64 %0, t; }"
        : "=r"(a) : "l"(p));
    return a;
}
__device__ __forceinline__ void mbar_init(uint32_t a, uint32_t cnt) {
    asm volatile("mbarrier.init.shared.b64 [%0], %1;" :: "r"(a), "r"(cnt) : "memory");
}
__device__ __forceinline__ void mbar_expect_tx(uint32_t a, uint32_t bytes) {
    asm volatile("mbarrier.arrive.expect_tx.shared.b64 _, [%0], %1;"
                 :: "r"(a), "r"(bytes) : "memory");
}
__device__ __forceinline__ void mbar_wait(uint32_t a, uint32_t parity) {
    asm volatile(
        "{\n\t.reg .pred P;\n"
        "W_%=:\n\t"
        "mbarrier.try_wait.parity.acquire.cta.shared::cta.b64 P, [%0], %1, 0x989680;\n\t"
        "@P bra D_%=;\n\t"
        "bra W_%=;\n"
        "D_%=:\n\t}"
        :: "r"(a), "r"(parity) : "memory");
}
__device__ __forceinline__ void bulk_g2s(uint32_t dst, const void* src,
                                         uint32_t bytes, uint32_t mbar) {
    asm volatile(
        "cp.async.bulk.shared::cluster.global.mbarrier::complete_tx::bytes "
        "[%0], [%1], %2, [%3];"
        :: "r"(dst), "l"(src), "r"(bytes), "r"(mbar) : "memory");
}

// ---------------------------------------------------------------------------
// Precompute stage 1: 96 blocks = 3 families x 32 u-slices.
// ---------------------------------------------------------------------------
__global__ void precompute1_kernel(
    const float* __restrict__ Wa_s, const float* __restrict__ Wa_v,
    const float* __restrict__ b_a,  const float* __restrict__ Wb_s,
    const float* __restrict__ Wb_v, const float* __restrict__ b_b,
    const float* __restrict__ W_ss, const float* __restrict__ W_vv,
    const float* __restrict__ W_sv, const float* __restrict__ W_vs)
{
    __shared__ float sA[MID], sB[MID], sC[MID], sAv[MID], sBv[MID];
    __shared__ float buf[6][32][33];

    const int tid = threadIdx.x;
    const int fam = blockIdx.x >> 5;
    const int u   = blockIdx.x & 31;
    if (tid < MID) {
        sA[tid]  = Wa_s[tid];
        sB[tid]  = Wb_s[tid];
        sC[tid]  = b_a[tid] + b_b[tid];
        sAv[tid] = Wa_v[tid];
        sBv[tid] = Wb_v[tid];
    }
    __syncthreads();

    const int v = tid >> 5;
    const int w = tid & 31;
    const int idx = u * 1024 + v * 32 + w;
    int nk;

    if (fam == 0) {
        float t = W_ss[idx];
        float Au = sA[u], Bu = sB[u], Cu = sC[u];
        float Av = sA[v], Bv = sB[v], Cv = sC[v];
        buf[0][v][w] = (Au * Av) * t;
        buf[1][v][w] = (Au * Bv + Bu * Av) * t;
        buf[2][v][w] = (Bu * Bv) * t;
        buf[3][v][w] = (Au * Cv + Cu * Av) * t;
        buf[4][v][w] = (Bu * Cv + Cu * Bv) * t;
        buf[5][v][w] = (Cu * Cv) * t;
        nk = 6;
    } else if (fam == 1) {
        float t = W_vv[idx];
        float Avu = sAv[u], Bvu = sBv[u], Avv = sAv[v], Bvv = sBv[v];
        buf[0][v][w] = (Avu * Avv) * t;
        buf[1][v][w] = (Avu * Bvv + Bvu * Avv) * t;
        buf[2][v][w] = (Bvu * Bvv) * t;
        nk = 3;
    } else {
        float tsv = W_sv[idx];
        float tvs = W_vs[idx];
        float Au = sA[u], Bu = sB[u], Cu = sC[u];
        float Avu = sAv[u], Bvu = sBv[u];
        float Av = sA[v], Bv = sB[v], Cv = sC[v];
        float Avv = sAv[v], Bvv = sBv[v];
        buf[0][v][w] = Au * Avv * tsv + Avu * Av * tvs;
        buf[1][v][w] = Bu * Avv * tsv + Avu * Bv * tvs;
        buf[2][v][w] = Cu * Avv * tsv + Avu * Cv * tvs;
        buf[3][v][w] = Au * Bvv * tsv + Bvu * Av * tvs;
        buf[4][v][w] = Bu * Bvv * tsv + Bvu * Bv * tvs;
        buf[5][v][w] = Cu * Bvv * tsv + Bvu * Cv * tvs;
        nk = 6;
    }
    __syncthreads();

    if (tid < nk * 32) {
        const int k = tid >> 5, ww = tid & 31;
        float s = 0.f;
        #pragma unroll
        for (int vv = 0; vv < 32; vv++) s += buf[k][vv][ww];
        g_stage[fam][u][k][ww] = s;
    }
}

// ---------------------------------------------------------------------------
// Precompute stage 2: u-reduction, Wd projection, scale folding.
// ---------------------------------------------------------------------------
__global__ void precompute2_kernel(const float* __restrict__ Wd_s,
                                   const float* __restrict__ Wd_v)
{
    __shared__ float sM[9][32], sG[3][32], sH[3][32];
    const int tid = threadIdx.x;

    if (tid < 480) {
        const int w = tid & 31;
        float s = 0.f;
        if (tid < 192) {
            const int k = tid >> 5;
            #pragma unroll
            for (int u = 0; u < 32; u++) s += g_stage[0][u][k][w];
            sM[k][w] = s;
        } else if (tid < 288) {
            const int k = (tid - 192) >> 5;
            #pragma unroll
            for (int u = 0; u < 32; u++) s += g_stage[1][u][k][w];
            sM[6 + k][w] = s;
        } else {
            const int k = (tid - 288) >> 5;
            #pragma unroll
            for (int u = 0; u < 32; u++) s += g_stage[2][u][k][w];
            if (k < 3) sG[k][w] = s; else sH[k - 3][w] = s;
        }
    }
    __syncthreads();

    if (tid < NNF) {
        const int vp = tid;
        const double INV_SQRT3 = 0.5773502691896258;
        const double PW_QQ_S = 0.02209708691207961;
        const double PW_QQ_V = 0.03827327723098713;
        const double PW_DOWN = 0.011048543456039805;
        const float scR  = (float)(PW_DOWN * PW_QQ_S);
        const float scR3 = (float)(PW_DOWN * PW_QQ_S * INV_SQRT3);
        const float scS  = (float)(PW_DOWN * INV_SQRT3 * PW_QQ_V * INV_SQRT3);

        #pragma unroll
        for (int k = 0; k < 9; k++) {
            float s = 0.f;
            #pragma unroll
            for (int uu = 0; uu < MID; uu++) s += sM[k][uu] * Wd_s[uu * NNF + vp];
            g_R[k][vp] = s * (k < 6 ? scR : scR3);
        }
        #pragma unroll
        for (int k = 0; k < 3; k++) {
            float sg = 0.f, sh = 0.f;
            #pragma unroll
            for (int uu = 0; uu < MID; uu++) {
                float wd = Wd_v[uu * NNF + vp];
                sg += sG[k][uu] * wd;
                sh += sH[k][uu] * wd;
            }
            g_S[k][vp]     = sg * scS;
            g_S[3 + k][vp] = sh * scS;
        }
    }
}

// ---------------------------------------------------------------------------
// Per-node partial (per-lane, 4 features) using packed f32x2 math.
// ---------------------------------------------------------------------------
__device__ __forceinline__ float node_partial(
    const u64 R2[9][2], const u64 S2[6][2],
    float4 fs, float4 fv0, float4 fv1, float4 fv2, float4 q0, float4 qi)
{
    const float a = qi.x, b = q0.x;
    const float g0 = qi.y, g1 = qi.z, g2 = qi.w;
    const float d0 = q0.y, d1 = q0.z, d2 = q0.w;
    const float ca2 = a * a, cab = a * b, cb2 = b * b;
    const float cg2 = g0 * g0 + g1 * g1 + g2 * g2;
    const float cgd = g0 * d0 + g1 * d1 + g2 * d2;
    const float cd2 = d0 * d0 + d1 * d1 + d2 * d2;

    const u64 C0 = pk2(ca2, ca2), C1 = pk2(cab, cab), C2 = pk2(cb2, cb2);
    const u64 CA = pk2(a, a),     CB = pk2(b, b);
    const u64 C6 = pk2(cg2, cg2), C7 = pk2(cgd, cgd), C8 = pk2(cd2, cd2);
    const u64 G0 = pk2(g0, g0), G1 = pk2(g1, g1), G2 = pk2(g2, g2);
    const u64 D0 = pk2(d0, d0), D1 = pk2(d1, d1), D2 = pk2(d2, d2);

    const float fv[12] = {fv0.x, fv0.y, fv0.z, fv0.w,
                          fv1.x, fv1.y, fv1.z, fv1.w,
                          fv2.x, fv2.y, fv2.z, fv2.w};
    const u64 fs2[2] = { pk2(fs.x, fs.y), pk2(fs.z, fs.w) };

    u64 acc = pk2(0.f, 0.f);
    #pragma unroll
    for (int h = 0; h < 2; h++) {
        u64 t = fma2(C0, R2[0][h], R2[5][h]);
        t = fma2(C1, R2[1][h], t);
        t = fma2(C2, R2[2][h], t);
        t = fma2(CA, R2[3][h], t);
        t = fma2(CB, R2[4][h], t);
        t = fma2(C6, R2[6][h], t);
        t = fma2(C7, R2[7][h], t);
        t = fma2(C8, R2[8][h], t);
        acc = fma2(fs2[h], t, acc);

        const u64 x0 = pk2(fv[6 * h + 0], fv[6 * h + 3]);
        const u64 x1 = pk2(fv[6 * h + 1], fv[6 * h + 4]);
        const u64 x2 = pk2(fv[6 * h + 2], fv[6 * h + 5]);
        u64 xg = mul2(G0, x0);
        xg = fma2(G1, x1, xg);
        xg = fma2(G2, x2, xg);
        u64 xd = mul2(D0, x0);
        xd = fma2(D1, x1, xd);
        xd = fma2(D2, x2, xd);
        u64 sg = fma2(CA, S2[0][h], S2[2][h]);
        sg = fma2(CB, S2[1][h], sg);
        u64 sh = fma2(CA, S2[3][h], S2[5][h]);
        sh = fma2(CB, S2[4][h], sh);
        acc = fma2(xg, sg, acc);
        acc = fma2(xd, sh, acc);
    }
    float lo, hi;
    upk2(acc, lo, hi);
    return lo + hi;
}

// ---------------------------------------------------------------------------
// Energy kernel: persistent blocks, 3-stage cp.async.bulk smem pipeline.
// Tile = 32 nodes (64KB node_feats + 2x512B charges). 16 warps: warp w
// computes nodes (2w, 2w+1) of the tile.
// ---------------------------------------------------------------------------
#define TILE_NODES   32
#define STAGES       3
#define NF_BYTES     (TILE_NODES * 4 * NNF * 4)       // 65536
#define CH_BYTES     (TILE_NODES * 4 * 4)             // 512
#define STAGE_BYTES  (NF_BYTES + 2 * CH_BYTES)        // 66560
#define SMEM_STAGE0  128
#define SMEM_TOTAL   (SMEM_STAGE0 + STAGES * STAGE_BYTES)

__global__ void __launch_bounds__(512, 1) energy_kernel(
    const float* __restrict__ nf,
    const float* __restrict__ c0,
    const float* __restrict__ ci,
    float* __restrict__ out, int N)
{
    extern __shared__ char smem[];
    const uint32_t smem_base = smem_u32(smem);
    const int tid  = threadIdx.x;
    const int lane = tid & 31;
    const int wid  = tid >> 5;          // 0..15

    // Load tables into registers (packed along feature axis).
    u64 R2[9][2], S2[6][2];
    #pragma unroll
    for (int k = 0; k < 9; k++) {
        float4 t = *(const float4*)&g_R[k][lane * 4];
        R2[k][0] = pk2(t.x, t.y); R2[k][1] = pk2(t.z, t.w);
    }
    #pragma unroll
    for (int k = 0; k < 6; k++) {
        float4 t = *(const float4*)&g_S[k][lane * 4];
        S2[k][0] = pk2(t.x, t.y); S2[k][1] = pk2(t.z, t.w);
    }

    const int T    = N / TILE_NODES;     // full tiles
    const int grid = gridDim.x;
    const int bid  = blockIdx.x;
    const int njt  = (T > bid) ? (T - bid + grid - 1) / grid : 0;

    if (tid == 0) {
        #pragma unroll
        for (int s = 0; s < STAGES; s++) mbar_init(smem_base + 8 * s, 1);
    }
    __syncthreads();

    // Prime the pipeline.
    if (tid == 0) {
        const int pre = njt < STAGES ? njt : STAGES;
        for (int j = 0; j < pre; j++) {
            const int t = bid + j * grid;
            const uint32_t stg = smem_base + SMEM_STAGE0 + j * STAGE_BYTES;
            const uint32_t mb  = smem_base + 8 * j;
            mbar_expect_tx(mb, STAGE_BYTES);
            bulk_g2s(stg, nf + (size_t)t * (TILE_NODES * 4 * NNF), NF_BYTES, mb);
            bulk_g2s(stg + NF_BYTES, c0 + (size_t)t * (TILE_NODES * 4), CH_BYTES, mb);
            bulk_g2s(stg + NF_BYTES + CH_BYTES,
                     ci + (size_t)t * (TILE_NODES * 4), CH_BYTES, mb);
        }
    }

    for (int j = 0; j < njt; j++) {
        const int rnd = j / STAGES;
        const int s   = j - rnd * STAGES;
        mbar_wait(smem_base + 8 * s, rnd & 1);

        const int t = bid + j * grid;
        const char* stg = smem + SMEM_STAGE0 + s * STAGE_BYTES;

        // Warp wid computes nodes (2*wid, 2*wid+1) of this tile.
        const int ln0 = 2 * wid;
        const char* rowA = stg + (size_t)ln0 * (4 * NNF * 4);
        const char* rowB = rowA + 4 * NNF * 4;

        float4 fsA  = *(const float4*)(rowA + lane * 16);
        float4 fvA0 = *(const float4*)(rowA + 512 + lane * 48);
        float4 fvA1 = *(const float4*)(rowA + 512 + lane * 48 + 16);
        float4 fvA2 = *(const float4*)(rowA + 512 + lane * 48 + 32);
        float4 q0A  = *(const float4*)(stg + NF_BYTES + ln0 * 16);
        float4 qiA  = *(const float4*)(stg + NF_BYTES + CH_BYTES + ln0 * 16);
        const float accA = node_partial(R2, S2, fsA, fvA0, fvA1, fvA2, q0A, qiA);

        float4 fsB  = *(const float4*)(rowB + lane * 16);
        float4 fvB0 = *(const float4*)(rowB + 512 + lane * 48);
        float4 fvB1 = *(const float4*)(rowB + 512 + lane * 48 + 16);
        float4 fvB2 = *(const float4*)(rowB + 512 + lane * 48 + 32);
        float4 q0B  = *(const float4*)(stg + NF_BYTES + ln0 * 16 + 16);
        float4 qiB  = *(const float4*)(stg + NF_BYTES + CH_BYTES + ln0 * 16 + 16);
        const float accB = node_partial(R2, S2, fsB, fvB0, fvB1, fvB2, q0B, qiB);

        u64 pr = pk2(accA, accB);
        #pragma unroll
        for (int off = 16; off; off >>= 1)
            pr = add2(pr, __shfl_down_sync(0xffffffffu, pr, off));
        if (lane == 0) {
            float2 o;
            upk2(pr, o.x, o.y);
            *(float2*)(out + (size_t)t * TILE_NODES + ln0) = o;
        }

        __syncthreads();   // all warps done reading stage s

        if (tid == 0 && j + STAGES < njt) {
            const int tn = bid + (j + STAGES) * grid;
            const uint32_t stgu = smem_base + SMEM_STAGE0 + s * STAGE_BYTES;
            const uint32_t mb   = smem_base + 8 * s;
            mbar_expect_tx(mb, STAGE_BYTES);
            bulk_g2s(stgu, nf + (size_t)tn * (TILE_NODES * 4 * NNF), NF_BYTES, mb);
            bulk_g2s(stgu + NF_BYTES, c0 + (size_t)tn * (TILE_NODES * 4), CH_BYTES, mb);
            bulk_g2s(stgu + NF_BYTES + CH_BYTES,
                     ci + (size_t)tn * (TILE_NODES * 4), CH_BYTES, mb);
        }
    }

    // Remainder nodes (N % 32) handled by last block via direct global loads.
    const int rem_start = T * TILE_NODES;
    if (bid == grid - 1 && rem_start < N) {
        for (int n = rem_start + wid; n < N; n += 16) {
            const float* row = nf + (size_t)n * (4 * NNF);
            float4 fs = *(const float4*)(row + lane * 4);
            const float* rv = row + NNF + 12 * lane;
            float4 f0 = *(const float4*)(rv);
            float4 f1 = *(const float4*)(rv + 4);
            float4 f2 = *(const float4*)(rv + 8);
            float4 q0 = *(const float4*)(c0 + 4 * (size_t)n);
            float4 qi = *(const float4*)(ci + 4 * (size_t)n);
            float acc = node_partial(R2, S2, fs, f0, f1, f2, q0, qi);
            #pragma unroll
            for (int off = 16; off; off >>= 1)
                acc += __shfl_down_sync(0xffffffffu, acc, off);
            if (lane == 0) out[n] = acc;
        }
    }
}

// ---------------------------------------------------------------------------
extern "C" void kernel_launch(void* const* d_in, const int* in_sizes, int n_in,
                              void* d_out, int out_size)
{
    const float* node_feats = (const float*)d_in[0];
    const float* charges_0  = (const float*)d_in[1];
    const float* charges_i  = (const float*)d_in[2];
    const float* Wa_s = (const float*)d_in[8];
    const float* Wa_v = (const float*)d_in[9];
    const float* b_a  = (const float*)d_in[10];
    const float* Wb_s = (const float*)d_in[11];
    const float* Wb_v = (const float*)d_in[12];
    const float* b_b  = (const float*)d_in[13];
    const float* W_ss = (const float*)d_in[14];
    const float* W_vv = (const float*)d_in[15];
    const float* W_sv = (const float*)d_in[16];
    const float* W_vs = (const float*)d_in[17];
    const float* Wd_s = (const float*)d_in[18];
    const float* Wd_v = (const float*)d_in[19];
    float* out = (float*)d_out;
    const int N = out_size;

    static bool attr_set = false;
    if (!attr_set) {
        cudaFuncSetAttribute(energy_kernel,
                             cudaFuncAttributeMaxDynamicSharedMemorySize,
                             SMEM_TOTAL);
        attr_set = true;
    }

    precompute1_kernel<<<96, 1024>>>(Wa_s, Wa_v, b_a, Wb_s, Wb_v, b_b,
                                     W_ss, W_vv, W_sv, W_vs);
    precompute2_kernel<<<1, 512>>>(Wd_s, Wd_v);
    energy_kernel<<<148, 512, SMEM_TOTAL>>>(node_feats, charges_0, charges_i,
                                            out, N);
}